// round 5
// baseline (speedup 1.0000x reference)
#include <cuda_runtime.h>

#define TPB 128

// Shared-memory layout (float offsets)
#define OFF_W11  0        // 128x8
#define OFF_B11  1024
#define OFF_W21  1152     // 128x8
#define OFF_B21  2176
#define OFF_W12  2304     // 128x128
#define OFF_B12  18688
#define OFF_W22  18816    // 128x128
#define OFF_B22  35200
#define OFF_WOUT 35328
#define OFF_YD   35456    // 128 x TPB tangent buffer, layout [h][tid]
#define SMEM_FLOATS (35456 + 128 * TPB)
#define SMEM_BYTES  (SMEM_FLOATS * 4)

__global__ __launch_bounds__(TPB, 1)
void net_kernel(const float* __restrict__ T, const float* __restrict__ L,
                const float* __restrict__ Ldot, const float* __restrict__ C,
                const float* __restrict__ w11, const float* __restrict__ b11,
                const float* __restrict__ w21, const float* __restrict__ b21,
                const float* __restrict__ w12, const float* __restrict__ b12,
                const float* __restrict__ w22, const float* __restrict__ b22,
                const float* __restrict__ wout, float* __restrict__ out)
{
    extern __shared__ float sm[];
    const int tid = threadIdx.x;

    // ---- cooperative weight load into shared ----
    for (int i = tid; i < 1024; i += TPB) sm[OFF_W11 + i] = w11[i];
    for (int i = tid; i < 128;  i += TPB) sm[OFF_B11 + i] = b11[i];
    for (int i = tid; i < 1024; i += TPB) sm[OFF_W21 + i] = w21[i];
    for (int i = tid; i < 128;  i += TPB) sm[OFF_B21 + i] = b21[i];
    for (int i = tid * 4; i < 16384; i += TPB * 4)
        *reinterpret_cast<float4*>(&sm[OFF_W12 + i]) = *reinterpret_cast<const float4*>(&w12[i]);
    for (int i = tid; i < 128;  i += TPB) sm[OFF_B12 + i] = b12[i];
    for (int i = tid * 4; i < 16384; i += TPB * 4)
        *reinterpret_cast<float4*>(&sm[OFF_W22 + i]) = *reinterpret_cast<const float4*>(&w22[i]);
    for (int i = tid; i < 128;  i += TPB) sm[OFF_B22 + i] = b22[i];
    for (int i = tid; i < 128;  i += TPB) sm[OFF_WOUT + i] = wout[i];
    __syncthreads();

    const int bid = blockIdx.x;

    if (bid < 512 || bid >= 1024) {
        // ---------------- forward-only path (T stream or center stream) ----------------
        const float* xptr;
        int out_idx;
        if (bid < 512) {
            int idx = bid * TPB + tid;
            xptr = T + (size_t)idx * 8;
            out_idx = idx;                 // v_t at [0, 65536)
        } else {
            int idx = (bid - 1024) * TPB + tid;
            xptr = C + (size_t)idx * 8;
            out_idx = 196608 + idx;        // v_center at [196608, 197120)
        }
        float4 xv0 = *reinterpret_cast<const float4*>(xptr);
        float4 xv1 = *reinterpret_cast<const float4*>(xptr + 4);
        float x0 = xv0.x, x1 = xv0.y, x2 = xv0.z, x3 = xv0.w;
        float x4 = xv1.x, x5 = xv1.y, x6 = xv1.z, x7 = xv1.w;

        float y[128];
        #pragma unroll
        for (int h = 0; h < 128; ++h) {
            float4 a0 = *reinterpret_cast<const float4*>(&sm[OFF_W11 + h * 8]);
            float4 a1 = *reinterpret_cast<const float4*>(&sm[OFF_W11 + h * 8 + 4]);
            float4 c0 = *reinterpret_cast<const float4*>(&sm[OFF_W21 + h * 8]);
            float4 c1 = *reinterpret_cast<const float4*>(&sm[OFF_W21 + h * 8 + 4]);
            float z1 = sm[OFF_B11 + h];
            z1 = fmaf(a0.x, x0, z1); z1 = fmaf(a0.y, x1, z1);
            z1 = fmaf(a0.z, x2, z1); z1 = fmaf(a0.w, x3, z1);
            z1 = fmaf(a1.x, x4, z1); z1 = fmaf(a1.y, x5, z1);
            z1 = fmaf(a1.z, x6, z1); z1 = fmaf(a1.w, x7, z1);
            float z2 = sm[OFF_B21 + h];
            z2 = fmaf(c0.x, x0, z2); z2 = fmaf(c0.y, x1, z2);
            z2 = fmaf(c0.z, x2, z2); z2 = fmaf(c0.w, x3, z2);
            z2 = fmaf(c1.x, x4, z2); z2 = fmaf(c1.y, x5, z2);
            z2 = fmaf(c1.z, x6, z2); z2 = fmaf(c1.w, x7, z2);
            y[h] = z1 * z2;
        }

        float acc = 0.f;
        for (int o = 0; o < 128; ++o) {
            const float* r1 = &sm[OFF_W12 + o * 128];
            const float* r2 = &sm[OFF_W22 + o * 128];
            float u1a = 0.f, u1b = 0.f, u2a = 0.f, u2b = 0.f;
            #pragma unroll
            for (int k = 0; k < 128; k += 4) {
                float4 a = *reinterpret_cast<const float4*>(&r1[k]);
                float4 b = *reinterpret_cast<const float4*>(&r2[k]);
                u1a = fmaf(a.x, y[k],     u1a);
                u1b = fmaf(a.y, y[k + 1], u1b);
                u1a = fmaf(a.z, y[k + 2], u1a);
                u1b = fmaf(a.w, y[k + 3], u1b);
                u2a = fmaf(b.x, y[k],     u2a);
                u2b = fmaf(b.y, y[k + 1], u2b);
                u2a = fmaf(b.z, y[k + 2], u2a);
                u2b = fmaf(b.w, y[k + 3], u2b);
            }
            float u1 = (u1a + u1b) + sm[OFF_B12 + o];
            float u2 = (u2a + u2b) + sm[OFF_B22 + o];
            acc = fmaf(sm[OFF_WOUT + o], u1 * u2, acc);
        }
        out[out_idx] = acc;
    } else {
        // ---------------- l stream: forward value + JVP (grad term) ----------------
        int idx = (bid - 512) * TPB + tid;
        const float* xptr = L    + (size_t)idx * 8;
        const float* dptr = Ldot + (size_t)idx * 8;
        float4 xv0 = *reinterpret_cast<const float4*>(xptr);
        float4 xv1 = *reinterpret_cast<const float4*>(xptr + 4);
        float4 dv0 = *reinterpret_cast<const float4*>(dptr);
        float4 dv1 = *reinterpret_cast<const float4*>(dptr + 4);
        float x0 = xv0.x, x1 = xv0.y, x2 = xv0.z, x3 = xv0.w;
        float x4 = xv1.x, x5 = xv1.y, x6 = xv1.z, x7 = xv1.w;
        float d0 = dv0.x, d1 = dv0.y, d2 = dv0.z, d3 = dv0.w;
        float d4 = dv1.x, d5 = dv1.y, d6 = dv1.z, d7 = dv1.w;

        float y[128];
        #pragma unroll
        for (int h = 0; h < 128; ++h) {
            float4 a0 = *reinterpret_cast<const float4*>(&sm[OFF_W11 + h * 8]);
            float4 a1 = *reinterpret_cast<const float4*>(&sm[OFF_W11 + h * 8 + 4]);
            float4 c0 = *reinterpret_cast<const float4*>(&sm[OFF_W21 + h * 8]);
            float4 c1 = *reinterpret_cast<const float4*>(&sm[OFF_W21 + h * 8 + 4]);
            float z1 = sm[OFF_B11 + h];
            z1 = fmaf(a0.x, x0, z1); z1 = fmaf(a0.y, x1, z1);
            z1 = fmaf(a0.z, x2, z1); z1 = fmaf(a0.w, x3, z1);
            z1 = fmaf(a1.x, x4, z1); z1 = fmaf(a1.y, x5, z1);
            z1 = fmaf(a1.z, x6, z1); z1 = fmaf(a1.w, x7, z1);
            float z2 = sm[OFF_B21 + h];
            z2 = fmaf(c0.x, x0, z2); z2 = fmaf(c0.y, x1, z2);
            z2 = fmaf(c0.z, x2, z2); z2 = fmaf(c0.w, x3, z2);
            z2 = fmaf(c1.x, x4, z2); z2 = fmaf(c1.y, x5, z2);
            z2 = fmaf(c1.z, x6, z2); z2 = fmaf(c1.w, x7, z2);
            // tangents (no bias in derivative)
            float t1 = a0.x * d0;
            t1 = fmaf(a0.y, d1, t1); t1 = fmaf(a0.z, d2, t1); t1 = fmaf(a0.w, d3, t1);
            t1 = fmaf(a1.x, d4, t1); t1 = fmaf(a1.y, d5, t1);
            t1 = fmaf(a1.z, d6, t1); t1 = fmaf(a1.w, d7, t1);
            float t2 = c0.x * d0;
            t2 = fmaf(c0.y, d1, t2); t2 = fmaf(c0.z, d2, t2); t2 = fmaf(c0.w, d3, t2);
            t2 = fmaf(c1.x, d4, t2); t2 = fmaf(c1.y, d5, t2);
            t2 = fmaf(c1.z, d6, t2); t2 = fmaf(c1.w, d7, t2);
            y[h] = z1 * z2;
            // yd = z1d*z2 + z1*z2d  -> stash in shared, [h][tid] (conflict-free)
            sm[OFF_YD + h * TPB + tid] = fmaf(t1, z2, z1 * t2);
        }

        float vacc = 0.f, gacc = 0.f;
        for (int o = 0; o < 128; ++o) {
            const float* r1 = &sm[OFF_W12 + o * 128];
            const float* r2 = &sm[OFF_W22 + o * 128];
            float u1a = 0.f, u1b = 0.f, u2a = 0.f, u2b = 0.f;
            float e1a = 0.f, e1b = 0.f, e2a = 0.f, e2b = 0.f;
            #pragma unroll
            for (int k = 0; k < 128; k += 4) {
                float4 a = *reinterpret_cast<const float4*>(&r1[k]);
                float4 b = *reinterpret_cast<const float4*>(&r2[k]);
                float yd0 = sm[OFF_YD + (k + 0) * TPB + tid];
                float yd1 = sm[OFF_YD + (k + 1) * TPB + tid];
                float yd2 = sm[OFF_YD + (k + 2) * TPB + tid];
                float yd3 = sm[OFF_YD + (k + 3) * TPB + tid];
                u1a = fmaf(a.x, y[k],     u1a);
                u1b = fmaf(a.y, y[k + 1], u1b);
                u1a = fmaf(a.z, y[k + 2], u1a);
                u1b = fmaf(a.w, y[k + 3], u1b);
                u2a = fmaf(b.x, y[k],     u2a);
                u2b = fmaf(b.y, y[k + 1], u2b);
                u2a = fmaf(b.z, y[k + 2], u2a);
                u2b = fmaf(b.w, y[k + 3], u2b);
                e1a = fmaf(a.x, yd0, e1a);
                e1b = fmaf(a.y, yd1, e1b);
                e1a = fmaf(a.z, yd2, e1a);
                e1b = fmaf(a.w, yd3, e1b);
                e2a = fmaf(b.x, yd0, e2a);
                e2b = fmaf(b.y, yd1, e2b);
                e2a = fmaf(b.z, yd2, e2a);
                e2b = fmaf(b.w, yd3, e2b);
            }
            float u1  = (u1a + u1b) + sm[OFF_B12 + o];
            float u2  = (u2a + u2b) + sm[OFF_B22 + o];
            float u1d = e1a + e1b;
            float u2d = e2a + e2b;
            float wo  = sm[OFF_WOUT + o];
            vacc = fmaf(wo, u1 * u2, vacc);
            gacc = fmaf(wo, fmaf(u1d, u2, u1 * u2d), gacc);
        }
        out[65536 + idx]  = vacc;   // v_y
        out[131072 + idx] = gacc;   // v_grad
    }
}

extern "C" void kernel_launch(void* const* d_in, const int* in_sizes, int n_in,
                              void* d_out, int out_size)
{
    const float* T    = (const float*)d_in[0];
    const float* L    = (const float*)d_in[1];
    const float* Ldot = (const float*)d_in[2];
    const float* C    = (const float*)d_in[3];
    const float* w11  = (const float*)d_in[4];
    const float* b11  = (const float*)d_in[5];
    const float* w21  = (const float*)d_in[6];
    const float* b21  = (const float*)d_in[7];
    const float* w12  = (const float*)d_in[8];
    const float* b12  = (const float*)d_in[9];
    const float* w22  = (const float*)d_in[10];
    const float* b22  = (const float*)d_in[11];
    const float* wout = (const float*)d_in[12];
    float* out = (float*)d_out;

    cudaFuncSetAttribute(net_kernel, cudaFuncAttributeMaxDynamicSharedMemorySize, SMEM_BYTES);

    // blocks: [0,512) -> T, [512,1024) -> l (fwd + JVP), [1024,1028) -> center
    net_kernel<<<1028, TPB, SMEM_BYTES>>>(T, L, Ldot, C,
                                          w11, b11, w21, b21,
                                          w12, b12, w22, b22,
                                          wout, out);
}

// round 7
// speedup vs baseline: 1.6195x; 1.6195x over previous
#include <cuda_runtime.h>

#define TPB 256
#define SPB 128   // samples per block (2 lanes per sample)

// shared-memory layout (float offsets) — weights only, 138.5 KB
#define OFF_W11  0        // 128x8
#define OFF_B11  1024
#define OFF_W21  1152     // 128x8
#define OFF_B21  2176
#define OFF_W12  2304     // 128x128
#define OFF_B12  18688
#define OFF_W22  18816    // 128x128
#define OFF_B22  35200
#define OFF_WOUT 35328
#define SMEM_FLOATS 35456
#define SMEM_BYTES  (SMEM_FLOATS * 4)

using u64 = unsigned long long;

__device__ __forceinline__ u64 fma2(u64 a, u64 b, u64 c) {
    u64 d; asm("fma.rn.f32x2 %0, %1, %2, %3;" : "=l"(d) : "l"(a), "l"(b), "l"(c)); return d;
}
__device__ __forceinline__ u64 mul2(u64 a, u64 b) {
    u64 d; asm("mul.rn.f32x2 %0, %1, %2;" : "=l"(d) : "l"(a), "l"(b)); return d;
}
__device__ __forceinline__ u64 pack2(float lo, float hi) {
    u64 d; asm("mov.b64 %0, {%1, %2};" : "=l"(d) : "f"(lo), "f"(hi)); return d;
}
__device__ __forceinline__ float red2(u64 v) {
    float lo, hi; asm("mov.b64 {%0, %1}, %2;" : "=f"(lo), "=f"(hi) : "l"(v)); return lo + hi;
}

__global__ __launch_bounds__(TPB, 1)
void net_kernel(const float* __restrict__ T, const float* __restrict__ L,
                const float* __restrict__ Ldot, const float* __restrict__ C,
                const float* __restrict__ w11, const float* __restrict__ b11,
                const float* __restrict__ w21, const float* __restrict__ b21,
                const float* __restrict__ w12, const float* __restrict__ b12,
                const float* __restrict__ w22, const float* __restrict__ b22,
                const float* __restrict__ wout, float* __restrict__ out)
{
    extern __shared__ float sm[];
    const int tid = threadIdx.x;

    // ---- cooperative weight load ----
    for (int i = tid; i < 1024; i += TPB) sm[OFF_W11 + i] = w11[i];
    for (int i = tid; i < 1024; i += TPB) sm[OFF_W21 + i] = w21[i];
    if (tid < 128) {
        sm[OFF_B11 + tid] = b11[tid];
        sm[OFF_B21 + tid] = b21[tid];
        sm[OFF_B12 + tid] = b12[tid];
        sm[OFF_B22 + tid] = b22[tid];
        sm[OFF_WOUT + tid] = wout[tid];
    }
    for (int i = tid * 4; i < 16384; i += TPB * 4)
        *reinterpret_cast<float4*>(&sm[OFF_W12 + i]) = *reinterpret_cast<const float4*>(&w12[i]);
    for (int i = tid * 4; i < 16384; i += TPB * 4)
        *reinterpret_cast<float4*>(&sm[OFF_W22 + i]) = *reinterpret_cast<const float4*>(&w22[i]);
    __syncthreads();

    const int p = tid & 1;        // lane parity: which hidden half this thread owns
    const int s = tid >> 1;       // sample slot within block
    const int bid = blockIdx.x;

    const float* wa  = &sm[OFF_W11 + p * 64 * 8];
    const float* wc  = &sm[OFF_W21 + p * 64 * 8];
    const float* sb1 = &sm[OFF_B11 + p * 64];
    const float* sb2 = &sm[OFF_B21 + p * 64];
    const float* w12p = &sm[OFF_W12 + p * 64];
    const float* w22p = &sm[OFF_W22 + p * 64];

    if (bid < 512 || bid >= 1024) {
        // ================= forward-only path (T or center) =================
        int idx, out_idx;
        const float* xptr;
        if (bid < 512) { idx = bid * SPB + s; xptr = T + (size_t)idx * 8; out_idx = idx; }
        else           { idx = (bid - 1024) * SPB + s; xptr = C + (size_t)idx * 8; out_idx = 196608 + idx; }

        ulonglong2 xa = *reinterpret_cast<const ulonglong2*>(xptr);      // {x01, x23}
        ulonglong2 xb = *reinterpret_cast<const ulonglong2*>(xptr + 4);  // {x45, x67}

        // ---- layer 1: this lane's 64 hidden units ----
        u64 ypk[32];
        float yprev = 0.f;
        #pragma unroll
        for (int j = 0; j < 64; ++j) {
            const ulonglong2* ra = reinterpret_cast<const ulonglong2*>(wa + j * 8);
            const ulonglong2* rc = reinterpret_cast<const ulonglong2*>(wc + j * 8);
            ulonglong2 q0 = ra[0], q1 = ra[1];
            ulonglong2 m0 = rc[0], m1 = rc[1];
            u64 a1 = mul2(q0.x, xa.x);
            u64 a2 = mul2(m0.x, xa.x);
            a1 = fma2(q0.y, xa.y, a1);
            a2 = fma2(m0.y, xa.y, a2);
            a1 = fma2(q1.x, xb.x, a1);
            a2 = fma2(m1.x, xb.x, a2);
            a1 = fma2(q1.y, xb.y, a1);
            a2 = fma2(m1.y, xb.y, a2);
            float z1 = red2(a1) + sb1[j];
            float z2 = red2(a2) + sb2[j];
            float yv = z1 * z2;
            if (j & 1) ypk[j >> 1] = pack2(yprev, yv);
            else       yprev = yv;
        }

        // ---- layer 2 + head ----
        float acc = 0.f;
        #pragma unroll 2
        for (int o = 0; o < 128; ++o) {
            const ulonglong2* r1 = reinterpret_cast<const ulonglong2*>(w12p + o * 128);
            const ulonglong2* r2 = reinterpret_cast<const ulonglong2*>(w22p + o * 128);
            u64 c10 = 0, c11 = 0, c20 = 0, c21 = 0;
            #pragma unroll
            for (int k = 0; k < 16; ++k) {
                ulonglong2 a = r1[k];
                ulonglong2 b = r2[k];
                c10 = fma2(a.x, ypk[2 * k],     c10);
                c20 = fma2(b.x, ypk[2 * k],     c20);
                c11 = fma2(a.y, ypk[2 * k + 1], c11);
                c21 = fma2(b.y, ypk[2 * k + 1], c21);
            }
            float u1 = red2(c10) + red2(c11);
            float u2 = red2(c20) + red2(c21);
            u1 += __shfl_xor_sync(0xffffffffu, u1, 1);
            u2 += __shfl_xor_sync(0xffffffffu, u2, 1);
            u1 += sm[OFF_B12 + o];
            u2 += sm[OFF_B22 + o];
            acc = fmaf(sm[OFF_WOUT + o], u1 * u2, acc);
        }
        if (p == 0) out[out_idx] = acc;
    } else {
        // ================= l stream: forward value + JVP =================
        int idx = (bid - 512) * SPB + s;
        const float* xptr = L    + (size_t)idx * 8;
        const float* dptr = Ldot + (size_t)idx * 8;
        ulonglong2 xa = *reinterpret_cast<const ulonglong2*>(xptr);
        ulonglong2 xb = *reinterpret_cast<const ulonglong2*>(xptr + 4);
        ulonglong2 da = *reinterpret_cast<const ulonglong2*>(dptr);
        ulonglong2 db = *reinterpret_cast<const ulonglong2*>(dptr + 4);

        u64 ypk[32], ydpk[32];
        float yprev = 0.f, ydprev = 0.f;
        #pragma unroll
        for (int j = 0; j < 64; ++j) {
            const ulonglong2* ra = reinterpret_cast<const ulonglong2*>(wa + j * 8);
            const ulonglong2* rc = reinterpret_cast<const ulonglong2*>(wc + j * 8);
            ulonglong2 q0 = ra[0], q1 = ra[1];
            ulonglong2 m0 = rc[0], m1 = rc[1];
            u64 a1 = mul2(q0.x, xa.x);
            u64 a2 = mul2(m0.x, xa.x);
            u64 t1 = mul2(q0.x, da.x);
            u64 t2 = mul2(m0.x, da.x);
            a1 = fma2(q0.y, xa.y, a1);
            a2 = fma2(m0.y, xa.y, a2);
            t1 = fma2(q0.y, da.y, t1);
            t2 = fma2(m0.y, da.y, t2);
            a1 = fma2(q1.x, xb.x, a1);
            a2 = fma2(m1.x, xb.x, a2);
            t1 = fma2(q1.x, db.x, t1);
            t2 = fma2(m1.x, db.x, t2);
            a1 = fma2(q1.y, xb.y, a1);
            a2 = fma2(m1.y, xb.y, a2);
            t1 = fma2(q1.y, db.y, t1);
            t2 = fma2(m1.y, db.y, t2);
            float z1  = red2(a1) + sb1[j];
            float z2  = red2(a2) + sb2[j];
            float z1d = red2(t1);
            float z2d = red2(t2);
            float yv  = z1 * z2;
            float ydv = fmaf(z1d, z2, z1 * z2d);
            if (j & 1) { ypk[j >> 1] = pack2(yprev, yv); ydpk[j >> 1] = pack2(ydprev, ydv); }
            else       { yprev = yv; ydprev = ydv; }
        }

        float vacc = 0.f, gacc = 0.f;
        #pragma unroll 1
        for (int o = 0; o < 128; ++o) {
            const ulonglong2* r1 = reinterpret_cast<const ulonglong2*>(w12p + o * 128);
            const ulonglong2* r2 = reinterpret_cast<const ulonglong2*>(w22p + o * 128);
            u64 c1 = 0, c2 = 0, e1 = 0, e2 = 0;
            #pragma unroll
            for (int k = 0; k < 16; ++k) {
                ulonglong2 a = r1[k];
                ulonglong2 b = r2[k];
                u64 y0 = ypk[2 * k],  y1 = ypk[2 * k + 1];
                u64 g0 = ydpk[2 * k], g1 = ydpk[2 * k + 1];
                c1 = fma2(a.x, y0, c1);
                c2 = fma2(b.x, y0, c2);
                e1 = fma2(a.x, g0, e1);
                e2 = fma2(b.x, g0, e2);
                c1 = fma2(a.y, y1, c1);
                c2 = fma2(b.y, y1, c2);
                e1 = fma2(a.y, g1, e1);
                e2 = fma2(b.y, g1, e2);
            }
            float u1  = red2(c1);
            float u2  = red2(c2);
            float u1d = red2(e1);
            float u2d = red2(e2);
            u1  += __shfl_xor_sync(0xffffffffu, u1, 1);
            u2  += __shfl_xor_sync(0xffffffffu, u2, 1);
            u1d += __shfl_xor_sync(0xffffffffu, u1d, 1);
            u2d += __shfl_xor_sync(0xffffffffu, u2d, 1);
            u1 += sm[OFF_B12 + o];
            u2 += sm[OFF_B22 + o];
            float wo = sm[OFF_WOUT + o];
            vacc = fmaf(wo, u1 * u2, vacc);
            gacc = fmaf(wo, fmaf(u1d, u2, u1 * u2d), gacc);
        }
        if (p == 0) {
            out[65536 + idx]  = vacc;   // v_y
            out[131072 + idx] = gacc;   // v_grad
        }
    }
}

extern "C" void kernel_launch(void* const* d_in, const int* in_sizes, int n_in,
                              void* d_out, int out_size)
{
    const float* T    = (const float*)d_in[0];
    const float* L    = (const float*)d_in[1];
    const float* Ldot = (const float*)d_in[2];
    const float* C    = (const float*)d_in[3];
    const float* w11  = (const float*)d_in[4];
    const float* b11  = (const float*)d_in[5];
    const float* w21  = (const float*)d_in[6];
    const float* b21  = (const float*)d_in[7];
    const float* w12  = (const float*)d_in[8];
    const float* b12  = (const float*)d_in[9];
    const float* w22  = (const float*)d_in[10];
    const float* b22  = (const float*)d_in[11];
    const float* wout = (const float*)d_in[12];
    float* out = (float*)d_out;

    cudaFuncSetAttribute(net_kernel, cudaFuncAttributeMaxDynamicSharedMemorySize, SMEM_BYTES);

    // blocks: [0,512) -> T, [512,1024) -> l (fwd + JVP), [1024,1028) -> center
    net_kernel<<<1028, TPB, SMEM_BYTES>>>(T, L, Ldot, C,
                                          w11, b11, w21, b21,
                                          w12, b12, w22, b22,
                                          wout, out);
}